// round 14
// baseline (speedup 1.0000x reference)
#include <cuda_runtime.h>

// SparseDenseMatMul: out[m,n] = sum_{i: rows[i]==m} vals[i] * A[cols[i], n]
// M = 100000, K = 100000, N = 64, NNZ = 1.6M
//
// Inputs (metadata order):
//   d_in[0] = vals (float, NNZ), d_in[1] = A (float, K*N),
//   d_in[2] = rows (int, NNZ),   d_in[3] = cols (int, NNZ)
// Output: float, M*N
//
// 2-kernel pipeline:
//   B: bin nnz into fixed-capacity per-row buckets (scalar ticket atomics),
//      4 nnz per thread. Counters start zero (module zero-init on first
//      call; phase C restores them to zero every call).
//   C: HALF-WARP per output row (16 lanes x float4 = 64 cols), two rows per
//      warp. Group-0 bucket loads are issued UNCONDITIONALLY, concurrently
//      with the counter load (they don't depend on it), removing one L2
//      trip from the per-warp critical path at zero register cost. The
//      inner loop is the register-lean Round-11 shape (32 regs, occ ~81%).
//      Unconsumed speculative loads read only valid scratch (zero-init or
//      prior-call leftovers), never fed into FMAs.

#define N_COLS     64
#define M_ROWS     100000
#define BUCKET_CAP 64
#define OVF_CAP    8192

__device__ int  d_cnt[M_ROWS];                           // zero-initialized
__device__ int2 d_bucket[(size_t)M_ROWS * BUCKET_CAP];   // (col, val-bits)
__device__ int  d_ovf_cnt;                               // zero-initialized
__device__ int  d_ovf[OVF_CAP];

// ---------------- Phase B: bin nnz into per-row buckets ----------------
__device__ __forceinline__ void bin_one(int r, int c, float v, int i) {
    int pos = atomicAdd(&d_cnt[r], 1);
    if (pos < BUCKET_CAP) {
        d_bucket[(size_t)r * BUCKET_CAP + pos] = make_int2(c, __float_as_int(v));
    } else {
        int o = atomicAdd(&d_ovf_cnt, 1);
        if (o < OVF_CAP) d_ovf[o] = i;
    }
}

__global__ void __launch_bounds__(256)
phaseB_scatter(const float4* __restrict__ vals4,
               const int4*   __restrict__ rows4,
               const int4*   __restrict__ cols4,
               int nnz) {
    int t  = blockIdx.x * blockDim.x + threadIdx.x;
    int i0 = t * 4;
    if (i0 >= nnz) return;

    int4   r4 = rows4[t];
    int4   c4 = cols4[t];
    float4 v4 = vals4[t];

    bin_one(r4.x, c4.x, v4.x, i0);
    if (i0 + 1 < nnz) bin_one(r4.y, c4.y, v4.y, i0 + 1);
    if (i0 + 2 < nnz) bin_one(r4.z, c4.z, v4.z, i0 + 2);
    if (i0 + 3 < nnz) bin_one(r4.w, c4.w, v4.w, i0 + 3);
}

// ---------------- Phase C: half-warp-per-row gather SpMM ---------------
__global__ void __launch_bounds__(256)
phaseC_spmm(const float4* __restrict__ A4,
            float4*       __restrict__ out4,
            const float*  __restrict__ vals,
            const int*    __restrict__ rows,
            const int*    __restrict__ cols,
            int m) {
    int gtid = blockIdx.x * blockDim.x + threadIdx.x;
    int w    = gtid >> 5;             // warp id: handles rows 2w, 2w+1
    int lane = threadIdx.x & 31;
    int half = lane >> 4;             // which row of the pair
    int sub  = lane & 15;             // float4 slice within the row
    int r0   = w << 1;
    if (r0 >= m) return;
    int row  = r0 + half;

    // Bucket pointer depends only on row, not on the counter. Phantom row
    // (m odd) clamps to row 0; its count is forced to 0 below.
    const int4* bk4 =
        (const int4*)(d_bucket + (size_t)(row < m ? row : 0) * BUCKET_CAP);

    // Issue the counter load AND group-0's four uniform bucket loads
    // back-to-back: they are independent, so both L2 trips overlap.
    int2 cnt2 = __ldg((const int2*)(d_cnt + r0));
    int4 q0 = __ldg(&bk4[0]);
    int4 q1 = __ldg(&bk4[1]);
    int4 q2 = __ldg(&bk4[2]);
    int4 q3 = __ldg(&bk4[3]);

    int c  = half ? cnt2.y : cnt2.x;
    if (row >= m) c = 0;
    int cc = c < BUCKET_CAP ? c : BUCKET_CAP;

    float4 acc = make_float4(0.f, 0.f, 0.f, 0.f);

    int k = 0;
    // 8 entries per iteration. First iteration consumes the preloaded q's;
    // later iterations reload them (register-lean Round-11 shape).
    for (; k + 8 <= cc; k += 8) {
        if (k != 0) {
            int h = k >> 1;
            q0 = __ldg(&bk4[h + 0]);
            q1 = __ldg(&bk4[h + 1]);
            q2 = __ldg(&bk4[h + 2]);
            q3 = __ldg(&bk4[h + 3]);
        }
        float4 a0 = __ldg(&A4[(size_t)q0.x * 16 + sub]);
        float4 a1 = __ldg(&A4[(size_t)q0.z * 16 + sub]);
        float4 a2 = __ldg(&A4[(size_t)q1.x * 16 + sub]);
        float4 a3 = __ldg(&A4[(size_t)q1.z * 16 + sub]);
        float4 a4 = __ldg(&A4[(size_t)q2.x * 16 + sub]);
        float4 a5 = __ldg(&A4[(size_t)q2.z * 16 + sub]);
        float4 a6 = __ldg(&A4[(size_t)q3.x * 16 + sub]);
        float4 a7 = __ldg(&A4[(size_t)q3.z * 16 + sub]);
        float v0 = __int_as_float(q0.y), v1 = __int_as_float(q0.w);
        float v2 = __int_as_float(q1.y), v3 = __int_as_float(q1.w);
        float v4 = __int_as_float(q2.y), v5 = __int_as_float(q2.w);
        float v6 = __int_as_float(q3.y), v7 = __int_as_float(q3.w);
        acc.x = fmaf(v0, a0.x, acc.x); acc.y = fmaf(v0, a0.y, acc.y);
        acc.z = fmaf(v0, a0.z, acc.z); acc.w = fmaf(v0, a0.w, acc.w);
        acc.x = fmaf(v1, a1.x, acc.x); acc.y = fmaf(v1, a1.y, acc.y);
        acc.z = fmaf(v1, a1.z, acc.z); acc.w = fmaf(v1, a1.w, acc.w);
        acc.x = fmaf(v2, a2.x, acc.x); acc.y = fmaf(v2, a2.y, acc.y);
        acc.z = fmaf(v2, a2.z, acc.z); acc.w = fmaf(v2, a2.w, acc.w);
        acc.x = fmaf(v3, a3.x, acc.x); acc.y = fmaf(v3, a3.y, acc.y);
        acc.z = fmaf(v3, a3.z, acc.z); acc.w = fmaf(v3, a3.w, acc.w);
        acc.x = fmaf(v4, a4.x, acc.x); acc.y = fmaf(v4, a4.y, acc.y);
        acc.z = fmaf(v4, a4.z, acc.z); acc.w = fmaf(v4, a4.w, acc.w);
        acc.x = fmaf(v5, a5.x, acc.x); acc.y = fmaf(v5, a5.y, acc.y);
        acc.z = fmaf(v5, a5.z, acc.z); acc.w = fmaf(v5, a5.w, acc.w);
        acc.x = fmaf(v6, a6.x, acc.x); acc.y = fmaf(v6, a6.y, acc.y);
        acc.z = fmaf(v6, a6.z, acc.z); acc.w = fmaf(v6, a6.w, acc.w);
        acc.x = fmaf(v7, a7.x, acc.x); acc.y = fmaf(v7, a7.y, acc.y);
        acc.z = fmaf(v7, a7.z, acc.z); acc.w = fmaf(v7, a7.w, acc.w);
    }
    // 2-wide tail.
    for (; k + 2 <= cc; k += 2) {
        int4 p = __ldg(&bk4[k >> 1]);
        float4 a0 = __ldg(&A4[(size_t)p.x * 16 + sub]);
        float4 a1 = __ldg(&A4[(size_t)p.z * 16 + sub]);
        float v0 = __int_as_float(p.y), v1 = __int_as_float(p.w);
        acc.x = fmaf(v0, a0.x, acc.x); acc.y = fmaf(v0, a0.y, acc.y);
        acc.z = fmaf(v0, a0.z, acc.z); acc.w = fmaf(v0, a0.w, acc.w);
        acc.x = fmaf(v1, a1.x, acc.x); acc.y = fmaf(v1, a1.y, acc.y);
        acc.z = fmaf(v1, a1.z, acc.z); acc.w = fmaf(v1, a1.w, acc.w);
    }
    // Scalar tail (0-1 entries).
    if (k < cc) {
        int2 e = __ldg(&((const int2*)bk4)[k]);
        float v  = __int_as_float(e.y);
        float4 a = __ldg(&A4[(size_t)e.x * 16 + sub]);
        acc.x = fmaf(v, a.x, acc.x); acc.y = fmaf(v, a.y, acc.y);
        acc.z = fmaf(v, a.z, acc.z); acc.w = fmaf(v, a.w, acc.w);
    }

    // Spill entries (unreachable for this dataset: max row degree ~40 << 64;
    // kept for correctness).
    if (c > BUCKET_CAP) {
        int n = d_ovf_cnt;
        if (n > OVF_CAP) n = OVF_CAP;
        for (int j = 0; j < n; j++) {
            int i = d_ovf[j];
            if (rows[i] == row) {
                float v  = vals[i];
                float4 a = __ldg(&A4[(size_t)cols[i] * 16 + sub]);
                acc.x = fmaf(v, a.x, acc.x); acc.y = fmaf(v, a.y, acc.y);
                acc.z = fmaf(v, a.z, acc.z); acc.w = fmaf(v, a.w, acc.w);
            }
        }
    }

    if (row < m) {
        out4[(size_t)row * 16 + sub] = acc;      // warp-wide 512B store
    }
    // One 8B store resets both rows' counters (phantom row harmless: its
    // counter was never incremented).
    if (lane == 0) *(int2*)(d_cnt + r0) = make_int2(0, 0);
    if (gtid == 0) d_ovf_cnt = 0;
}

extern "C" void kernel_launch(void* const* d_in, const int* in_sizes, int n_in,
                              void* d_out, int out_size) {
    const float* vals = (const float*)d_in[0];
    const float* A    = (const float*)d_in[1];
    const int*   rows = (const int*)d_in[2];
    const int*   cols = (const int*)d_in[3];
    float*       out  = (float*)d_out;

    int nnz = in_sizes[0];
    int m   = out_size / N_COLS;
    if (m > M_ROWS) m = M_ROWS;   // scratch capacity bound (shapes are fixed)

    // Phase B: bin into buckets (4 nnz per thread)
    {
        int threads = 256;
        int quads   = (nnz + 3) / 4;
        int blocks  = (quads + threads - 1) / threads;
        phaseB_scatter<<<blocks, threads>>>((const float4*)vals,
                                            (const int4*)rows,
                                            (const int4*)cols, nnz);
    }
    // Phase C: half-warp-per-row gather SpMM (2 rows per warp)
    {
        int threads   = 256;                     // 8 warps = 16 rows / block
        int row_pairs = (m + 1) / 2;
        int blocks    = (row_pairs * 32 + threads - 1) / threads;
        phaseC_spmm<<<blocks, threads>>>((const float4*)A, (float4*)out,
                                         vals, rows, cols, m);
    }
}

// round 16
// speedup vs baseline: 1.1119x; 1.1119x over previous
#include <cuda_runtime.h>

// SparseDenseMatMul: out[m,n] = sum_{i: rows[i]==m} vals[i] * A[cols[i], n]
// M = 100000, K = 100000, N = 64, NNZ = 1.6M
//
// Inputs (metadata order):
//   d_in[0] = vals (float, NNZ), d_in[1] = A (float, K*N),
//   d_in[2] = rows (int, NNZ),   d_in[3] = cols (int, NNZ)
// Output: float, M*N
//
// 2-kernel pipeline (composition of best-measured variants):
//   B: bin nnz into fixed-capacity per-row buckets (scalar ticket atomics),
//      4 nnz per thread (Round-12 shape, ~18us incl. overheads).
//   C: HALF-WARP per output row (16 lanes x float4 = 64 cols), two rows per
//      warp; Round-11 loop shape — bucket loads at the top of each
//      iteration, NOTHING live across the loop back-edge except the
//      accumulator (32 regs, occ ~81%, measured 40.6us). Register rule
//      learned R12/R14: any cross-iteration live value costs ~10 regs and
//      ~25% occupancy — do not reintroduce prefetch.

#define N_COLS     64
#define M_ROWS     100000
#define BUCKET_CAP 64
#define OVF_CAP    8192

__device__ int  d_cnt[M_ROWS];                           // zero-initialized
__device__ int2 d_bucket[(size_t)M_ROWS * BUCKET_CAP];   // (col, val-bits)
__device__ int  d_ovf_cnt;                               // zero-initialized
__device__ int  d_ovf[OVF_CAP];

// ---------------- Phase B: bin nnz into per-row buckets ----------------
__device__ __forceinline__ void bin_one(int r, int c, float v, int i) {
    int pos = atomicAdd(&d_cnt[r], 1);
    if (pos < BUCKET_CAP) {
        d_bucket[(size_t)r * BUCKET_CAP + pos] = make_int2(c, __float_as_int(v));
    } else {
        int o = atomicAdd(&d_ovf_cnt, 1);
        if (o < OVF_CAP) d_ovf[o] = i;
    }
}

__global__ void __launch_bounds__(256)
phaseB_scatter(const float4* __restrict__ vals4,
               const int4*   __restrict__ rows4,
               const int4*   __restrict__ cols4,
               int nnz) {
    int t  = blockIdx.x * blockDim.x + threadIdx.x;
    int i0 = t * 4;
    if (i0 >= nnz) return;

    int4   r4 = rows4[t];
    int4   c4 = cols4[t];
    float4 v4 = vals4[t];

    bin_one(r4.x, c4.x, v4.x, i0);
    if (i0 + 1 < nnz) bin_one(r4.y, c4.y, v4.y, i0 + 1);
    if (i0 + 2 < nnz) bin_one(r4.z, c4.z, v4.z, i0 + 2);
    if (i0 + 3 < nnz) bin_one(r4.w, c4.w, v4.w, i0 + 3);
}

// ---------------- Phase C: half-warp-per-row gather SpMM ---------------
__global__ void __launch_bounds__(256)
phaseC_spmm(const float4* __restrict__ A4,
            float4*       __restrict__ out4,
            const float*  __restrict__ vals,
            const int*    __restrict__ rows,
            const int*    __restrict__ cols,
            int m) {
    int gtid = blockIdx.x * blockDim.x + threadIdx.x;
    int w    = gtid >> 5;             // warp id: handles rows 2w, 2w+1
    int lane = threadIdx.x & 31;
    int half = lane >> 4;             // which row of the pair
    int sub  = lane & 15;             // float4 slice within the row
    int r0   = w << 1;
    if (r0 >= m) return;
    int row  = r0 + half;

    // Both rows' counters with one uniform 8B load (r0 even -> aligned).
    int2 cnt2 = __ldg((const int2*)(d_cnt + r0));
    int c  = half ? cnt2.y : cnt2.x;
    if (row >= m) c = 0;              // m odd, phantom second row
    int cc = c < BUCKET_CAP ? c : BUCKET_CAP;

    // Bucket for this half's row (512B-aligned). Phantom row clamps to
    // row 0; cc==0 so nothing is consumed.
    const int4* bk4 =
        (const int4*)(d_bucket + (size_t)(row < m ? row : 0) * BUCKET_CAP);

    float4 acc = make_float4(0.f, 0.f, 0.f, 0.f);

    int k = 0;
    // 8 entries per iteration: 4 uniform int4 loads + 8 independent gathers
    // (per half; warp-wide each LDG instruction serves both rows).
    for (; k + 8 <= cc; k += 8) {
        int h = k >> 1;
        int4 p0 = __ldg(&bk4[h + 0]);
        int4 p1 = __ldg(&bk4[h + 1]);
        int4 p2 = __ldg(&bk4[h + 2]);
        int4 p3 = __ldg(&bk4[h + 3]);
        float4 a0 = __ldg(&A4[(size_t)p0.x * 16 + sub]);
        float4 a1 = __ldg(&A4[(size_t)p0.z * 16 + sub]);
        float4 a2 = __ldg(&A4[(size_t)p1.x * 16 + sub]);
        float4 a3 = __ldg(&A4[(size_t)p1.z * 16 + sub]);
        float4 a4 = __ldg(&A4[(size_t)p2.x * 16 + sub]);
        float4 a5 = __ldg(&A4[(size_t)p2.z * 16 + sub]);
        float4 a6 = __ldg(&A4[(size_t)p3.x * 16 + sub]);
        float4 a7 = __ldg(&A4[(size_t)p3.z * 16 + sub]);
        float v0 = __int_as_float(p0.y), v1 = __int_as_float(p0.w);
        float v2 = __int_as_float(p1.y), v3 = __int_as_float(p1.w);
        float v4 = __int_as_float(p2.y), v5 = __int_as_float(p2.w);
        float v6 = __int_as_float(p3.y), v7 = __int_as_float(p3.w);
        acc.x = fmaf(v0, a0.x, acc.x); acc.y = fmaf(v0, a0.y, acc.y);
        acc.z = fmaf(v0, a0.z, acc.z); acc.w = fmaf(v0, a0.w, acc.w);
        acc.x = fmaf(v1, a1.x, acc.x); acc.y = fmaf(v1, a1.y, acc.y);
        acc.z = fmaf(v1, a1.z, acc.z); acc.w = fmaf(v1, a1.w, acc.w);
        acc.x = fmaf(v2, a2.x, acc.x); acc.y = fmaf(v2, a2.y, acc.y);
        acc.z = fmaf(v2, a2.z, acc.z); acc.w = fmaf(v2, a2.w, acc.w);
        acc.x = fmaf(v3, a3.x, acc.x); acc.y = fmaf(v3, a3.y, acc.y);
        acc.z = fmaf(v3, a3.z, acc.z); acc.w = fmaf(v3, a3.w, acc.w);
        acc.x = fmaf(v4, a4.x, acc.x); acc.y = fmaf(v4, a4.y, acc.y);
        acc.z = fmaf(v4, a4.z, acc.z); acc.w = fmaf(v4, a4.w, acc.w);
        acc.x = fmaf(v5, a5.x, acc.x); acc.y = fmaf(v5, a5.y, acc.y);
        acc.z = fmaf(v5, a5.z, acc.z); acc.w = fmaf(v5, a5.w, acc.w);
        acc.x = fmaf(v6, a6.x, acc.x); acc.y = fmaf(v6, a6.y, acc.y);
        acc.z = fmaf(v6, a6.z, acc.z); acc.w = fmaf(v6, a6.w, acc.w);
        acc.x = fmaf(v7, a7.x, acc.x); acc.y = fmaf(v7, a7.y, acc.y);
        acc.z = fmaf(v7, a7.z, acc.z); acc.w = fmaf(v7, a7.w, acc.w);
    }
    // 2-wide tail.
    for (; k + 2 <= cc; k += 2) {
        int4 p = __ldg(&bk4[k >> 1]);
        float4 a0 = __ldg(&A4[(size_t)p.x * 16 + sub]);
        float4 a1 = __ldg(&A4[(size_t)p.z * 16 + sub]);
        float v0 = __int_as_float(p.y), v1 = __int_as_float(p.w);
        acc.x = fmaf(v0, a0.x, acc.x); acc.y = fmaf(v0, a0.y, acc.y);
        acc.z = fmaf(v0, a0.z, acc.z); acc.w = fmaf(v0, a0.w, acc.w);
        acc.x = fmaf(v1, a1.x, acc.x); acc.y = fmaf(v1, a1.y, acc.y);
        acc.z = fmaf(v1, a1.z, acc.z); acc.w = fmaf(v1, a1.w, acc.w);
    }
    // Scalar tail (0-1 entries).
    if (k < cc) {
        int2 e = __ldg(&((const int2*)bk4)[k]);
        float v  = __int_as_float(e.y);
        float4 a = __ldg(&A4[(size_t)e.x * 16 + sub]);
        acc.x = fmaf(v, a.x, acc.x); acc.y = fmaf(v, a.y, acc.y);
        acc.z = fmaf(v, a.z, acc.z); acc.w = fmaf(v, a.w, acc.w);
    }

    // Spill entries (unreachable for this dataset: max row degree ~40 << 64;
    // kept for correctness).
    if (c > BUCKET_CAP) {
        int n = d_ovf_cnt;
        if (n > OVF_CAP) n = OVF_CAP;
        for (int j = 0; j < n; j++) {
            int i = d_ovf[j];
            if (rows[i] == row) {
                float v  = vals[i];
                float4 a = __ldg(&A4[(size_t)cols[i] * 16 + sub]);
                acc.x = fmaf(v, a.x, acc.x); acc.y = fmaf(v, a.y, acc.y);
                acc.z = fmaf(v, a.z, acc.z); acc.w = fmaf(v, a.w, acc.w);
            }
        }
    }

    if (row < m) {
        out4[(size_t)row * 16 + sub] = acc;      // warp-wide 512B store
    }
    // One 8B store resets both rows' counters (phantom row harmless: its
    // counter was never incremented).
    if (lane == 0) *(int2*)(d_cnt + r0) = make_int2(0, 0);
    if (gtid == 0) d_ovf_cnt = 0;
}

extern "C" void kernel_launch(void* const* d_in, const int* in_sizes, int n_in,
                              void* d_out, int out_size) {
    const float* vals = (const float*)d_in[0];
    const float* A    = (const float*)d_in[1];
    const int*   rows = (const int*)d_in[2];
    const int*   cols = (const int*)d_in[3];
    float*       out  = (float*)d_out;

    int nnz = in_sizes[0];
    int m   = out_size / N_COLS;
    if (m > M_ROWS) m = M_ROWS;   // scratch capacity bound (shapes are fixed)

    // Phase B: bin into buckets (4 nnz per thread)
    {
        int threads = 256;
        int quads   = (nnz + 3) / 4;
        int blocks  = (quads + threads - 1) / threads;
        phaseB_scatter<<<blocks, threads>>>((const float4*)vals,
                                            (const int4*)rows,
                                            (const int4*)cols, nnz);
    }
    // Phase C: half-warp-per-row gather SpMM (2 rows per warp)
    {
        int threads   = 256;                     // 8 warps = 16 rows / block
        int row_pairs = (m + 1) / 2;
        int blocks    = (row_pairs * 32 + threads - 1) / threads;
        phaseC_spmm<<<blocks, threads>>>((const float4*)A, (float4*)out,
                                         vals, rows, cols, m);
    }
}

// round 17
// speedup vs baseline: 1.1172x; 1.0047x over previous
#include <cuda_runtime.h>

// SparseDenseMatMul: out[m,n] = sum_{i: rows[i]==m} vals[i] * A[cols[i], n]
// M = 100000, K = 100000, N = 64, NNZ = 1.6M
//
// Inputs (metadata order):
//   d_in[0] = vals (float, NNZ), d_in[1] = A (float, K*N),
//   d_in[2] = rows (int, NNZ),   d_in[3] = cols (int, NNZ)
// Output: float, M*N
//
// 2-kernel pipeline:
//   B: bin nnz into fixed-capacity per-row buckets (scalar ticket atomics),
//      4 nnz per thread.
//   C: HALF-WARP per output row (16 lanes x float4 = 64 cols), two rows per
//      warp. The first 32 bucket entries of both rows are staged into SMEM
//      via cp.async (LDGSTS: no data registers held -> occupancy preserved),
//      issued concurrently with the counter load. The gather loop reads
//      entries from SMEM (LDS ~29cyc) instead of L2 (~240cyc), cutting the
//      per-warp serial chain from ~5 L2 trips to ~3. Entries beyond 32
//      (P ~1e-4 per row) fall back to direct global reads.
//      Register rule (R12/R14): nothing lives across the gather-loop
//      back-edge except the accumulator.

#define N_COLS     64
#define M_ROWS     100000
#define BUCKET_CAP 64
#define STAGE_ENT  32            // entries staged in smem per row
#define OVF_CAP    8192

__device__ int  d_cnt[M_ROWS];                           // zero-initialized
__device__ int2 d_bucket[(size_t)M_ROWS * BUCKET_CAP];   // (col, val-bits)
__device__ int  d_ovf_cnt;                               // zero-initialized
__device__ int  d_ovf[OVF_CAP];

// ---------------- Phase B: bin nnz into per-row buckets ----------------
__device__ __forceinline__ void bin_one(int r, int c, float v, int i) {
    int pos = atomicAdd(&d_cnt[r], 1);
    if (pos < BUCKET_CAP) {
        d_bucket[(size_t)r * BUCKET_CAP + pos] = make_int2(c, __float_as_int(v));
    } else {
        int o = atomicAdd(&d_ovf_cnt, 1);
        if (o < OVF_CAP) d_ovf[o] = i;
    }
}

__global__ void __launch_bounds__(256)
phaseB_scatter(const float4* __restrict__ vals4,
               const int4*   __restrict__ rows4,
               const int4*   __restrict__ cols4,
               int nnz) {
    int t  = blockIdx.x * blockDim.x + threadIdx.x;
    int i0 = t * 4;
    if (i0 >= nnz) return;

    int4   r4 = rows4[t];
    int4   c4 = cols4[t];
    float4 v4 = vals4[t];

    bin_one(r4.x, c4.x, v4.x, i0);
    if (i0 + 1 < nnz) bin_one(r4.y, c4.y, v4.y, i0 + 1);
    if (i0 + 2 < nnz) bin_one(r4.z, c4.z, v4.z, i0 + 2);
    if (i0 + 3 < nnz) bin_one(r4.w, c4.w, v4.w, i0 + 3);
}

// ---------------- Phase C: half-warp-per-row gather SpMM ---------------
__global__ void __launch_bounds__(256)
phaseC_spmm(const float4* __restrict__ A4,
            float4*       __restrict__ out4,
            const float*  __restrict__ vals,
            const int*    __restrict__ rows,
            const int*    __restrict__ cols,
            int m) {
    // 8 warps/block, each warp stages 2 rows x 16 int4 chunks = 32 int4.
    __shared__ int4 s_bk[8][32];

    int gtid = blockIdx.x * blockDim.x + threadIdx.x;
    int w    = gtid >> 5;             // warp id: handles rows 2w, 2w+1
    int lane = threadIdx.x & 31;
    int wib  = threadIdx.x >> 5;      // warp index in block (0..7)
    int half = lane >> 4;             // which row of the pair
    int sub  = lane & 15;             // float4 slice within the row
    int r0   = w << 1;
    if (r0 >= m) return;
    int row  = r0 + half;

    // ---- Stage first 32 entries of both rows' buckets into smem via
    // cp.async, issued BEFORE the counter load resolves (independent).
    {
        int crow = r0 + (lane >> 4);              // lanes 0-15: row r0; 16-31: r0+1
        if (crow >= m) crow = r0;                 // phantom row: harmless source
        const int4* src =
            (const int4*)(d_bucket + (size_t)crow * BUCKET_CAP) + (lane & 15);
        unsigned dst = (unsigned)__cvta_generic_to_shared(&s_bk[wib][lane]);
        asm volatile("cp.async.cg.shared.global [%0], [%1], 16;\n"
                     :: "r"(dst), "l"(src));
        asm volatile("cp.async.commit_group;\n" ::: "memory");
    }

    // Counter load overlaps with the cp.async above.
    int2 cnt2 = __ldg((const int2*)(d_cnt + r0));
    int c  = half ? cnt2.y : cnt2.x;
    if (row >= m) c = 0;              // m odd, phantom second row
    int cc = c < BUCKET_CAP ? c : BUCKET_CAP;

    asm volatile("cp.async.wait_group 0;\n" ::: "memory");
    __syncwarp();

    const int4* sbk = &s_bk[wib][half << 4];      // this half's 16 staged chunks
    const int4* bk4 =                              // global fallback (entries>=32)
        (const int4*)(d_bucket + (size_t)(row < m ? row : 0) * BUCKET_CAP);

    float4 acc = make_float4(0.f, 0.f, 0.f, 0.f);

    int ccs = cc < STAGE_ENT ? cc : STAGE_ENT;    // staged portion
    int k = 0;
    // 8 entries per iteration: 4 smem chunk reads (broadcast) + 8 gathers.
    for (; k + 8 <= ccs; k += 8) {
        int h = k >> 1;
        int4 p0 = sbk[h + 0];
        int4 p1 = sbk[h + 1];
        int4 p2 = sbk[h + 2];
        int4 p3 = sbk[h + 3];
        float4 a0 = __ldg(&A4[(size_t)p0.x * 16 + sub]);
        float4 a1 = __ldg(&A4[(size_t)p0.z * 16 + sub]);
        float4 a2 = __ldg(&A4[(size_t)p1.x * 16 + sub]);
        float4 a3 = __ldg(&A4[(size_t)p1.z * 16 + sub]);
        float4 a4 = __ldg(&A4[(size_t)p2.x * 16 + sub]);
        float4 a5 = __ldg(&A4[(size_t)p2.z * 16 + sub]);
        float4 a6 = __ldg(&A4[(size_t)p3.x * 16 + sub]);
        float4 a7 = __ldg(&A4[(size_t)p3.z * 16 + sub]);
        float v0 = __int_as_float(p0.y), v1 = __int_as_float(p0.w);
        float v2 = __int_as_float(p1.y), v3 = __int_as_float(p1.w);
        float v4 = __int_as_float(p2.y), v5 = __int_as_float(p2.w);
        float v6 = __int_as_float(p3.y), v7 = __int_as_float(p3.w);
        acc.x = fmaf(v0, a0.x, acc.x); acc.y = fmaf(v0, a0.y, acc.y);
        acc.z = fmaf(v0, a0.z, acc.z); acc.w = fmaf(v0, a0.w, acc.w);
        acc.x = fmaf(v1, a1.x, acc.x); acc.y = fmaf(v1, a1.y, acc.y);
        acc.z = fmaf(v1, a1.z, acc.z); acc.w = fmaf(v1, a1.w, acc.w);
        acc.x = fmaf(v2, a2.x, acc.x); acc.y = fmaf(v2, a2.y, acc.y);
        acc.z = fmaf(v2, a2.z, acc.z); acc.w = fmaf(v2, a2.w, acc.w);
        acc.x = fmaf(v3, a3.x, acc.x); acc.y = fmaf(v3, a3.y, acc.y);
        acc.z = fmaf(v3, a3.z, acc.z); acc.w = fmaf(v3, a3.w, acc.w);
        acc.x = fmaf(v4, a4.x, acc.x); acc.y = fmaf(v4, a4.y, acc.y);
        acc.z = fmaf(v4, a4.z, acc.z); acc.w = fmaf(v4, a4.w, acc.w);
        acc.x = fmaf(v5, a5.x, acc.x); acc.y = fmaf(v5, a5.y, acc.y);
        acc.z = fmaf(v5, a5.z, acc.z); acc.w = fmaf(v5, a5.w, acc.w);
        acc.x = fmaf(v6, a6.x, acc.x); acc.y = fmaf(v6, a6.y, acc.y);
        acc.z = fmaf(v6, a6.z, acc.z); acc.w = fmaf(v6, a6.w, acc.w);
        acc.x = fmaf(v7, a7.x, acc.x); acc.y = fmaf(v7, a7.y, acc.y);
        acc.z = fmaf(v7, a7.z, acc.z); acc.w = fmaf(v7, a7.w, acc.w);
    }
    // 2-wide staged tail.
    for (; k + 2 <= ccs; k += 2) {
        int4 p = sbk[k >> 1];
        float4 a0 = __ldg(&A4[(size_t)p.x * 16 + sub]);
        float4 a1 = __ldg(&A4[(size_t)p.z * 16 + sub]);
        float v0 = __int_as_float(p.y), v1 = __int_as_float(p.w);
        acc.x = fmaf(v0, a0.x, acc.x); acc.y = fmaf(v0, a0.y, acc.y);
        acc.z = fmaf(v0, a0.z, acc.z); acc.w = fmaf(v0, a0.w, acc.w);
        acc.x = fmaf(v1, a1.x, acc.x); acc.y = fmaf(v1, a1.y, acc.y);
        acc.z = fmaf(v1, a1.z, acc.z); acc.w = fmaf(v1, a1.w, acc.w);
    }
    // Scalar staged tail (0-1 entries).
    if (k < ccs) {
        int4 p = sbk[k >> 1];
        float v  = __int_as_float(p.y);
        float4 a = __ldg(&A4[(size_t)p.x * 16 + sub]);
        acc.x = fmaf(v, a.x, acc.x); acc.y = fmaf(v, a.y, acc.y);
        acc.z = fmaf(v, a.z, acc.z); acc.w = fmaf(v, a.w, acc.w);
        k++;
    }
    // Unstaged entries (cc > 32; P ~1e-4 per row): direct global reads.
    for (k = STAGE_ENT; k + 2 <= cc; k += 2) {
        int4 p = __ldg(&bk4[k >> 1]);
        float4 a0 = __ldg(&A4[(size_t)p.x * 16 + sub]);
        float4 a1 = __ldg(&A4[(size_t)p.z * 16 + sub]);
        float v0 = __int_as_float(p.y), v1 = __int_as_float(p.w);
        acc.x = fmaf(v0, a0.x, acc.x); acc.y = fmaf(v0, a0.y, acc.y);
        acc.z = fmaf(v0, a0.z, acc.z); acc.w = fmaf(v0, a0.w, acc.w);
        acc.x = fmaf(v1, a1.x, acc.x); acc.y = fmaf(v1, a1.y, acc.y);
        acc.z = fmaf(v1, a1.z, acc.z); acc.w = fmaf(v1, a1.w, acc.w);
    }
    if (k < cc && k >= STAGE_ENT) {
        int2 e = __ldg(&((const int2*)bk4)[k]);
        float v  = __int_as_float(e.y);
        float4 a = __ldg(&A4[(size_t)e.x * 16 + sub]);
        acc.x = fmaf(v, a.x, acc.x); acc.y = fmaf(v, a.y, acc.y);
        acc.z = fmaf(v, a.z, acc.z); acc.w = fmaf(v, a.w, acc.w);
    }

    // Spill entries (unreachable for this dataset: max row degree ~40 << 64;
    // kept for correctness).
    if (c > BUCKET_CAP) {
        int n = d_ovf_cnt;
        if (n > OVF_CAP) n = OVF_CAP;
        for (int j = 0; j < n; j++) {
            int i = d_ovf[j];
            if (rows[i] == row) {
                float v  = vals[i];
                float4 a = __ldg(&A4[(size_t)cols[i] * 16 + sub]);
                acc.x = fmaf(v, a.x, acc.x); acc.y = fmaf(v, a.y, acc.y);
                acc.z = fmaf(v, a.z, acc.z); acc.w = fmaf(v, a.w, acc.w);
            }
        }
    }

    if (row < m) {
        out4[(size_t)row * 16 + sub] = acc;      // warp-wide 512B store
    }
    // One 8B store resets both rows' counters (phantom row harmless).
    if (lane == 0) *(int2*)(d_cnt + r0) = make_int2(0, 0);
    if (gtid == 0) d_ovf_cnt = 0;
}

extern "C" void kernel_launch(void* const* d_in, const int* in_sizes, int n_in,
                              void* d_out, int out_size) {
    const float* vals = (const float*)d_in[0];
    const float* A    = (const float*)d_in[1];
    const int*   rows = (const int*)d_in[2];
    const int*   cols = (const int*)d_in[3];
    float*       out  = (float*)d_out;

    int nnz = in_sizes[0];
    int m   = out_size / N_COLS;
    if (m > M_ROWS) m = M_ROWS;   // scratch capacity bound (shapes are fixed)

    // Phase B: bin into buckets (4 nnz per thread)
    {
        int threads = 256;
        int quads   = (nnz + 3) / 4;
        int blocks  = (quads + threads - 1) / threads;
        phaseB_scatter<<<blocks, threads>>>((const float4*)vals,
                                            (const int4*)rows,
                                            (const int4*)cols, nnz);
    }
    // Phase C: half-warp-per-row gather SpMM (2 rows per warp, smem-staged)
    {
        int threads   = 256;                     // 8 warps = 16 rows / block
        int row_pairs = (m + 1) / 2;
        int blocks    = (row_pairs * 32 + threads - 1) / threads;
        phaseC_spmm<<<blocks, threads>>>((const float4*)A, (float4*)out,
                                         vals, rows, cols, m);
    }
}